// round 15
// baseline (speedup 1.0000x reference)
#include <cuda_runtime.h>
#include <cuda_fp16.h>
#include <mma.h>
#include <cstdint>
#include <cstddef>

using namespace nvcuda;

#define E_ 8
#define T_ 1024
#define D_ 2048
#define H_ 5632

// fp16 operand copies + y scratch. x/W1/W2 converted by gate work-stealing pool,
// W3 by the gate streaming side-channel.
__device__ __align__(256) __half g_hx [(size_t)E_ * T_ * D_];
__device__ __align__(256) __half g_hw1[(size_t)E_ * D_ * H_];
__device__ __align__(256) __half g_hw2[(size_t)E_ * D_ * H_];
__device__ __align__(256) __half g_hw3[(size_t)E_ * H_ * D_];
__device__ __align__(256) __half g_hy [(size_t)E_ * T_ * H_];

// conversion pool state (zeroed by init kernel each call)
__device__ int g_next;
__device__ int g_done[32];

// ---------------- helpers ----------------
union Pack4 { uint2 u; __half2 h[2]; };
__device__ __forceinline__ uint2 pack4(float4 v) {
    Pack4 p;
    p.h[0] = __floats2half2_rn(v.x, v.y);
    p.h[1] = __floats2half2_rn(v.z, v.w);
    return p.u;
}
__device__ __forceinline__ float silu_mul(float v1, float v2) {
    return v2 * v1 * (1.0f / (1.0f + __expf(-v1)));
}
__device__ __forceinline__ void cp_async16(void* s, const void* g) {
    uint32_t sa = (uint32_t)__cvta_generic_to_shared(s);
    asm volatile("cp.async.cg.shared.global [%0], [%1], 16;" :: "r"(sa), "l"(g));
}
__device__ __forceinline__ void cp_commit() { asm volatile("cp.async.commit_group;"); }
template <int N>
__device__ __forceinline__ void cp_wait() { asm volatile("cp.async.wait_group %0;" :: "n"(N)); }

// ---------------- pool geometry ----------------
// Slab j converts: x[:, :, j*64:(j+1)*64]  (131072 float4)
//                + W1/W2[:, j*64:(j+1)*64, :] (2 x 720896 float4)
constexpr int F4_X_SLAB  = 131072;           // 8192 rows x 16 f4-cols
constexpr int F4_W_SLAB  = 720896;           // 512 rows x 1408 f4-cols (per mat)
constexpr int F4_SLAB    = F4_X_SLAB + 2 * F4_W_SLAB;  // 1,572,864
constexpr int PIECE_F4   = 2048;             // 256 thr x 8 f4
constexpr int PIECES     = F4_SLAB / PIECE_F4;          // 768
constexpr int NSLAB      = 32;
constexpr int C_TOT      = NSLAB * PIECES;              // 24576

constexpr size_t W3C = (size_t)E_ * H_ * D_ / 4;

__global__ void init_pool() {
    if (threadIdx.x < 32) g_done[threadIdx.x] = 0;
    if (threadIdx.x == 32) g_next = 0;
}

// ---------------- tiling (R11/R14 config) ----------------
constexpr int BM  = 128;
constexpr int BK  = 64;
constexpr int BN1 = 64;
constexpr int BN2 = 128;
constexpr int LDA  = BK  + 8;   // 72
constexpr int LDB1 = BN1 + 8;   // 72
constexpr int LDB2 = BN2 + 8;   // 136
constexpr int STG = 3;

constexpr int A_SLAB  = BM * LDA;    // 9216 halfs
constexpr int B1_SLAB = BK * LDB1;   // 4608
constexpr int B2_SLAB = BK * LDB2;   // 8704

constexpr size_t SMEM_CORE1 = (size_t)STG * (A_SLAB + 2 * B1_SLAB) * sizeof(__half); // 110592
constexpr size_t SMEM1 = SMEM_CORE1 + 16;                                             // +ctrl slot
constexpr size_t SMEM2 = (size_t)STG * (A_SLAB + B2_SLAB) * sizeof(__half);           // 107520

constexpr int NK1 = D_ / BK;          // 32
constexpr int NK2 = H_ / BK;          // 88
constexpr int W3_PER_CTA = (int)(W3C / (8ull * 88 * 8));  // 4096 = 256thr x 16 iters

// =====================================================================
// Kernel 1: y = silu(x@W1) * (x@W2)
//  + work-stealing fp32->fp16 conversion of x/W1/W2 (slab-ordered pool)
//  + W3 fp32->fp16 streaming side-channel
// 256 threads, 8 warps (2M x 4N). Warp tile 64x16 per gate. 2 CTAs/SM.
// Grid: (T/BM, H/BN1, E) = (8, 88, 8)
// =====================================================================
__global__ void __launch_bounds__(256, 2)
ffn_gate_h(const float* __restrict__ Xsrc, const float* __restrict__ W1src,
           const float* __restrict__ W2src, const float* __restrict__ W3src)
{
    extern __shared__ __align__(128) __half smem[];
    __half* sA  = smem;                    // [STG][A_SLAB]
    __half* sB1 = sA  + STG * A_SLAB;      // [STG][B1_SLAB]
    __half* sB2 = sB1 + STG * B1_SLAB;     // [STG][B1_SLAB]
    int* ctrl = (int*)((char*)smem + SMEM_CORE1);   // 1-int broadcast slot

    const int tid  = threadIdx.x;
    const int warp = tid >> 5;
    const int lane = tid & 31;
    const int wm   = warp >> 2;   // 0..1
    const int wn   = warp & 3;    // 0..3
    const int e  = blockIdx.z;
    const int m0 = blockIdx.x * BM;
    const int n0 = blockIdx.y * BN1;
    const __half* Ax  = g_hx  + (size_t)e * T_ * D_;
    const __half* B1g = g_hw1 + (size_t)e * D_ * H_;
    const __half* B2g = g_hw2 + (size_t)e * D_ * H_;

    // ---- conversion chunk (all 256 threads) ----
    auto convert_chunk = [&](int c) {
        const int j    = c / PIECES;
        const int base = (c - j * PIECES) * PIECE_F4;
        #pragma unroll
        for (int i = 0; i < 8; i++) {
            int q = base + tid + i * 256;
            const float4* src; uint2* dst; size_t idx;
            if (q < F4_X_SLAB) {
                int row = q >> 4, cc = q & 15;           // row in [0,8192)
                idx = (size_t)row * 512 + j * 16 + cc;   // D/4 = 512 f4 per row
                src = (const float4*)Xsrc; dst = (uint2*)g_hx;
            } else {
                int q2  = q - F4_X_SLAB;
                int mat = q2 / F4_W_SLAB;
                int q3  = q2 - mat * F4_W_SLAB;
                int row = q3 / 1408;                     // [0,512): e*64+dd
                int col = q3 - row * 1408;
                int e2 = row >> 6, dd = row & 63;
                idx = ((size_t)(e2 * D_ + j * 64 + dd)) * 1408 + col;
                src = (const float4*)(mat ? W2src : W1src);
                dst = (uint2*)(mat ? g_hw2 : g_hw1);
            }
            dst[idx] = pack4(src[idx]);
        }
    };

    // ---- steal-until-ready (uniform across CTA) ----
    auto ensure_ready = [&](int j) {
        while (true) {
            if (tid == 0) {
                int cmd;
                if (atomicAdd(&g_done[j], 0) >= PIECES) cmd = -1;        // ready
                else {
                    int c = atomicAdd(&g_next, 1);
                    cmd = (c < C_TOT) ? c : -2;                          // steal | wait
                }
                ctrl[0] = cmd;
            }
            __syncthreads();
            int cmd = ctrl[0];
            __syncthreads();
            if (cmd == -1) break;
            if (cmd >= 0) {
                convert_chunk(cmd);
                __threadfence();              // publish before counting
                __syncthreads();
                if (tid == 0) atomicAdd(&g_done[cmd / PIECES], 1);
            } else {
                __nanosleep(200);
            }
        }
        __threadfence();                      // acquire before consuming
    };

    // W3 side-channel
    const size_t cta_lin = (size_t)blockIdx.x + 8ull * (blockIdx.y + 88ull * blockIdx.z);
    const size_t w3_base = cta_lin * W3_PER_CTA + tid;
    const float4* w3s = (const float4*)W3src;
    uint2*        w3d = (uint2*)g_hw3;

    wmma::fragment<wmma::accumulator, 16, 16, 16, float> c1[4], c2[4];
    #pragma unroll
    for (int i = 0; i < 4; i++) {
        wmma::fill_fragment(c1[i], 0.0f);
        wmma::fill_fragment(c2[i], 0.0f);
    }

    auto load = [&](int s, int kt) {
        const int k0 = kt * BK;
        #pragma unroll
        for (int i = 0; i < 4; i++) {
            int u = tid + i * 256;
            int row = u >> 3, ch = u & 7;
            cp_async16(sA + s * A_SLAB + row * LDA + ch * 8,
                       Ax + (size_t)(m0 + row) * D_ + k0 + ch * 8);
        }
        #pragma unroll
        for (int i = 0; i < 4; i++) {
            int u = tid + i * 256;
            int mat = u >> 9;
            int rem = u & 511;
            int r = rem >> 3, ch = rem & 7;
            const __half* src = (mat ? B2g : B1g) + (size_t)(k0 + r) * H_ + n0 + ch * 8;
            __half* dst = (mat ? sB2 : sB1) + s * B1_SLAB + r * LDB1 + ch * 8;
            cp_async16(dst, src);
        }
        cp_commit();
    };

    ensure_ready(0);
    load(0, 0);
    ensure_ready(1);
    load(1, 1);

    for (int kt = 0; kt < NK1; kt++) {
        const int s = kt % 3;
        if (kt + 1 < NK1) cp_wait<1>(); else cp_wait<0>();
        __syncthreads();

        float4 w3v;
        const size_t w3i = w3_base + (size_t)kt * 256;
        if (kt < 16) w3v = w3s[w3i];

        if (kt + 2 < NK1) {
            ensure_ready(kt + 2);
            load((kt + 2) % 3, kt + 2);
        }

        const __half* aW  = sA  + s * A_SLAB  + (wm * 64) * LDA;
        const __half* b1W = sB1 + s * B1_SLAB + wn * 16;
        const __half* b2W = sB2 + s * B1_SLAB + wn * 16;
        #pragma unroll
        for (int kk = 0; kk < BK / 16; kk++) {
            wmma::fragment<wmma::matrix_a, 16, 16, 16, __half, wmma::row_major> a[4];
            #pragma unroll
            for (int i = 0; i < 4; i++)
                wmma::load_matrix_sync(a[i], aW + i * 16 * LDA + kk * 16, LDA);
            {
                wmma::fragment<wmma::matrix_b, 16, 16, 16, __half, wmma::row_major> b;
                wmma::load_matrix_sync(b, b1W + kk * 16 * LDB1, LDB1);
                #pragma unroll
                for (int i = 0; i < 4; i++)
                    wmma::mma_sync(c1[i], a[i], b, c1[i]);
            }
            {
                wmma::fragment<wmma::matrix_b, 16, 16, 16, __half, wmma::row_major> b;
                wmma::load_matrix_sync(b, b2W + kk * 16 * LDB1, LDB1);
                #pragma unroll
                for (int i = 0; i < 4; i++)
                    wmma::mma_sync(c2[i], a[i], b, c2[i]);
            }
        }

        if (kt < 16) w3d[w3i] = pack4(w3v);
        // no bottom barrier
    }

    // Epilogue: silu(c1)*c2 -> fp16 y via per-warp 64x16 fp32 smem patch
    __syncthreads();
    float* pw = (float*)smem + warp * (64 * 16);
    #pragma unroll
    for (int i = 0; i < 4; i++) {
        #pragma unroll
        for (int t = 0; t < c1[i].num_elements; t++)
            c1[i].x[t] = silu_mul(c1[i].x[t], c2[i].x[t]);
        wmma::store_matrix_sync(pw + i * 16 * 16, c1[i], 16, wmma::mem_row_major);
    }
    __syncwarp();
    __half* yb = g_hy + (size_t)e * T_ * H_ + (size_t)(m0 + wm * 64) * H_ + n0 + wn * 16;
    #pragma unroll
    for (int i = 0; i < 16; i++) {
        int u = lane + i * 32;
        int row = u >> 3, col2 = u & 7;
        float2 v = *(float2*)(pw + row * 16 + col2 * 2);
        *(__half2*)(yb + (size_t)row * H_ + col2 * 2) = __floats2half2_rn(v.x, v.y);
    }
}

// =====================================================================
// Kernel 2: out = y @ W3   (all fp16, R11/R14 config)
// =====================================================================
__global__ void __launch_bounds__(256, 2)
ffn_down_h(float* __restrict__ Out)
{
    extern __shared__ __align__(128) __half smem[];
    __half* sA = smem;
    __half* sB = sA + STG * A_SLAB;

    const int tid  = threadIdx.x;
    const int warp = tid >> 5;
    const int wm   = warp >> 2;
    const int wn   = warp & 3;
    const int e  = blockIdx.z;
    const int m0 = blockIdx.x * BM;
    const int n0 = blockIdx.y * BN2;
    const __half* Ay = g_hy  + (size_t)e * T_ * H_;
    const __half* Bg = g_hw3 + (size_t)e * H_ * D_;

    wmma::fragment<wmma::accumulator, 16, 16, 16, float> c[4][2];
    #pragma unroll
    for (int i = 0; i < 4; i++)
        #pragma unroll
        for (int j = 0; j < 2; j++)
            wmma::fill_fragment(c[i][j], 0.0f);

    auto load = [&](int s, int kt) {
        const int k0 = kt * BK;
        #pragma unroll
        for (int i = 0; i < 4; i++) {
            int u = tid + i * 256;
            int row = u >> 3, ch = u & 7;
            cp_async16(sA + s * A_SLAB + row * LDA + ch * 8,
                       Ay + (size_t)(m0 + row) * H_ + k0 + ch * 8);
        }
        #pragma unroll
        for (int i = 0; i < 4; i++) {
            int u = tid + i * 256;
            int r = u >> 4, ch = u & 15;
            cp_async16(sB + s * B2_SLAB + r * LDB2 + ch * 8,
                       Bg + (size_t)(k0 + r) * D_ + n0 + ch * 8);
        }
        cp_commit();
    };

    load(0, 0);
    load(1, 1);

    for (int kt = 0; kt < NK2; kt++) {
        const int s = kt % 3;
        if (kt + 1 < NK2) cp_wait<1>(); else cp_wait<0>();
        __syncthreads();
        if (kt + 2 < NK2) load((kt + 2) % 3, kt + 2);

        const __half* aW = sA + s * A_SLAB  + (wm * 64) * LDA;
        const __half* bW = sB + s * B2_SLAB + wn * 32;
        #pragma unroll
        for (int kk = 0; kk < BK / 16; kk++) {
            wmma::fragment<wmma::matrix_a, 16, 16, 16, __half, wmma::row_major> a[4];
            #pragma unroll
            for (int i = 0; i < 4; i++)
                wmma::load_matrix_sync(a[i], aW + i * 16 * LDA + kk * 16, LDA);
            wmma::fragment<wmma::matrix_b, 16, 16, 16, __half, wmma::row_major> b[2];
            #pragma unroll
            for (int j = 0; j < 2; j++)
                wmma::load_matrix_sync(b[j], bW + kk * 16 * LDB2 + j * 16, LDB2);
            #pragma unroll
            for (int i = 0; i < 4; i++)
                #pragma unroll
                for (int j = 0; j < 2; j++)
                    wmma::mma_sync(c[i][j], a[i], b[j], c[i][j]);
        }
        // no bottom barrier
    }

    #pragma unroll
    for (int i = 0; i < 4; i++)
        #pragma unroll
        for (int j = 0; j < 2; j++)
            wmma::store_matrix_sync(
                Out + (size_t)e * T_ * D_
                    + (size_t)(m0 + wm * 64 + i * 16) * D_ + (n0 + wn * 32 + j * 16),
                c[i][j], D_, wmma::mem_row_major);
}

// =====================================================================
extern "C" void kernel_launch(void* const* d_in, const int* in_sizes, int n_in,
                              void* d_out, int out_size)
{
    const float* x  = (const float*)d_in[0];
    const float* w1 = (const float*)d_in[1];
    const float* w2 = (const float*)d_in[2];
    const float* w3 = (const float*)d_in[3];
    float* out = (float*)d_out;
    (void)in_sizes; (void)n_in; (void)out_size;

    cudaFuncSetAttribute(ffn_gate_h, cudaFuncAttributeMaxDynamicSharedMemorySize, (int)SMEM1);
    cudaFuncSetAttribute(ffn_down_h, cudaFuncAttributeMaxDynamicSharedMemorySize, (int)SMEM2);

    init_pool<<<1, 64>>>();

    dim3 g1(T_ / BM, H_ / BN1, E_);        // (8, 88, 8)
    ffn_gate_h<<<g1, 256, SMEM1>>>(x, w1, w2, w3);

    dim3 g2(T_ / BM, D_ / BN2, E_);        // (8, 16, 8)
    ffn_down_h<<<g2, 256, SMEM2>>>(out);
}

// round 16
// speedup vs baseline: 1.5061x; 1.5061x over previous
#include <cuda_runtime.h>
#include <cuda_fp16.h>
#include <mma.h>
#include <cstdint>
#include <cstddef>

using namespace nvcuda;

#define E_ 8
#define T_ 1024
#define D_ 2048
#define H_ 5632

// fp16 operand copies + y scratch. W3 converted by gate side-channel.
__device__ __align__(256) __half g_hx [(size_t)E_ * T_ * D_];
__device__ __align__(256) __half g_hw1[(size_t)E_ * D_ * H_];
__device__ __align__(256) __half g_hw2[(size_t)E_ * D_ * H_];
__device__ __align__(256) __half g_hw3[(size_t)E_ * H_ * D_];
__device__ __align__(256) __half g_hy [(size_t)E_ * T_ * H_];

// ---------------- helpers ----------------
union Pack4 { uint2 u; __half2 h[2]; };
__device__ __forceinline__ uint2 pack4(float4 v) {
    Pack4 p;
    p.h[0] = __floats2half2_rn(v.x, v.y);
    p.h[1] = __floats2half2_rn(v.z, v.w);
    return p.u;
}
__device__ __forceinline__ float silu_mul(float v1, float v2) {
    return v2 * v1 * (1.0f / (1.0f + __expf(-v1)));
}
__device__ __forceinline__ void cp_async16(void* s, const void* g) {
    uint32_t sa = (uint32_t)__cvta_generic_to_shared(s);
    asm volatile("cp.async.cg.shared.global [%0], [%1], 16;" :: "r"(sa), "l"(g));
}
__device__ __forceinline__ void cp_commit() { asm volatile("cp.async.commit_group;"); }
template <int N>
__device__ __forceinline__ void cp_wait() { asm volatile("cp.async.wait_group %0;" :: "n"(N)); }

// ---------- cvt3: x/W1/W2 fp32->fp16, 2 independent 32B pairs per thread ----------
constexpr size_t XC  = (size_t)E_ * T_ * D_ / 4;   // float4 chunks (even)
constexpr size_t WC  = (size_t)E_ * D_ * H_ / 4;   // (even)
constexpr size_t W3C = (size_t)E_ * H_ * D_ / 4;
constexpr size_t TOT3 = XC + 2 * WC;
constexpr size_t TOT3P = TOT3 / 2;                 // pairs (XC, WC even -> region-safe)

__device__ __forceinline__ void cvt_pair(size_t i,
    const float* __restrict__ x, const float* __restrict__ w1,
    const float* __restrict__ w2)
{
    const float4* src; uint2* dst; size_t off;
    if (i < XC)           { src = (const float4*)x;  dst = (uint2*)g_hx;  off = i; }
    else if (i < XC + WC) { src = (const float4*)w1; dst = (uint2*)g_hw1; off = i - XC; }
    else                  { src = (const float4*)w2; dst = (uint2*)g_hw2; off = i - XC - WC; }
    float4 a = src[off], b = src[off + 1];
    uint2 pa = pack4(a), pb = pack4(b);
    *(uint4*)(dst + off) = make_uint4(pa.x, pa.y, pb.x, pb.y);
}

__global__ void __launch_bounds__(256)
cvt3_kernel(const float* __restrict__ x, const float* __restrict__ w1,
            const float* __restrict__ w2)
{
    // 2 independent pairs per thread (doubled MLP), split halves of the range
    size_t j = (size_t)blockIdx.x * blockDim.x + threadIdx.x;
    constexpr size_t HALF = TOT3P / 2;
    if (j < HALF) {
        cvt_pair(2 * j, x, w1, w2);
        cvt_pair(2 * (j + HALF), x, w1, w2);
    } else if (j < TOT3P - HALF) {
        // covers the odd remainder element if TOT3P is odd (it isn't; safe guard)
        cvt_pair(2 * (j + HALF), x, w1, w2);
    }
}

// ---------------- tiling: 2 CTAs/SM, 3-stage pipeline (R11/R14 config) ----------------
constexpr int BM  = 128;
constexpr int BK  = 64;
constexpr int BN1 = 64;
constexpr int BN2 = 128;
constexpr int LDA  = BK  + 8;   // 72
constexpr int LDB1 = BN1 + 8;   // 72
constexpr int LDB2 = BN2 + 8;   // 136
constexpr int STG = 3;

constexpr int A_SLAB  = BM * LDA;    // 9216 halfs
constexpr int B1_SLAB = BK * LDB1;   // 4608
constexpr int B2_SLAB = BK * LDB2;   // 8704

constexpr size_t SMEM1 = (size_t)STG * (A_SLAB + 2 * B1_SLAB) * sizeof(__half); // 110592
constexpr size_t SMEM2 = (size_t)STG * (A_SLAB + B2_SLAB) * sizeof(__half);     // 107520

constexpr int NK1 = D_ / BK;          // 32
constexpr int NK2 = H_ / BK;          // 88
constexpr int W3_PER_CTA = (int)(W3C / (8ull * 88 * 8));  // 4096 = 256thr x 16 iters

// =====================================================================
// Kernel 1: y = silu(x@W1) * (x@W2)  + W3 fp32->fp16 side-channel
// 256 threads, 8 warps (2M x 4N). Warp tile 64x16 per gate. 2 CTAs/SM.
// Grid: (T/BM, H/BN1, E) = (8, 88, 8)
// =====================================================================
__global__ void __launch_bounds__(256, 2)
ffn_gate_h(const float* __restrict__ W3src)
{
    extern __shared__ __align__(128) __half smem[];
    __half* sA  = smem;                    // [STG][A_SLAB]
    __half* sB1 = sA  + STG * A_SLAB;      // [STG][B1_SLAB]
    __half* sB2 = sB1 + STG * B1_SLAB;     // [STG][B1_SLAB]

    const int tid  = threadIdx.x;
    const int warp = tid >> 5;
    const int lane = tid & 31;
    const int wm   = warp >> 2;   // 0..1
    const int wn   = warp & 3;    // 0..3
    const int e  = blockIdx.z;
    const int m0 = blockIdx.x * BM;
    const int n0 = blockIdx.y * BN1;
    const __half* Ax  = g_hx  + (size_t)e * T_ * D_;
    const __half* B1g = g_hw1 + (size_t)e * D_ * H_;
    const __half* B2g = g_hw2 + (size_t)e * D_ * H_;

    const size_t cta_lin = (size_t)blockIdx.x + 8ull * (blockIdx.y + 88ull * blockIdx.z);
    const size_t w3_base = cta_lin * W3_PER_CTA + tid;
    const float4* w3s = (const float4*)W3src;
    uint2*        w3d = (uint2*)g_hw3;

    wmma::fragment<wmma::accumulator, 16, 16, 16, float> c1[4], c2[4];
    #pragma unroll
    for (int i = 0; i < 4; i++) {
        wmma::fill_fragment(c1[i], 0.0f);
        wmma::fill_fragment(c2[i], 0.0f);
    }

    auto load = [&](int s, int kt) {
        const int k0 = kt * BK;
        #pragma unroll
        for (int i = 0; i < 4; i++) {
            int u = tid + i * 256;
            int row = u >> 3, ch = u & 7;
            cp_async16(sA + s * A_SLAB + row * LDA + ch * 8,
                       Ax + (size_t)(m0 + row) * D_ + k0 + ch * 8);
        }
        #pragma unroll
        for (int i = 0; i < 4; i++) {
            int u = tid + i * 256;
            int mat = u >> 9;
            int rem = u & 511;
            int r = rem >> 3, ch = rem & 7;
            const __half* src = (mat ? B2g : B1g) + (size_t)(k0 + r) * H_ + n0 + ch * 8;
            __half* dst = (mat ? sB2 : sB1) + s * B1_SLAB + r * LDB1 + ch * 8;
            cp_async16(dst, src);
        }
        cp_commit();
    };

    load(0, 0);
    load(1, 1);

    int s = 0;                 // manual stage rotation (no % in loop)
    int sl = 2;                // stage for the next load
    for (int kt = 0; kt < NK1; kt++) {
        if (kt + 1 < NK1) cp_wait<1>(); else cp_wait<0>();
        __syncthreads();

        float4 w3v;
        const size_t w3i = w3_base + (size_t)kt * 256;
        if (kt < 16) w3v = w3s[w3i];

        if (kt + 2 < NK1) {
            load(sl, kt + 2);
            if (++sl == 3) sl = 0;
        }

        const __half* aW  = sA  + s * A_SLAB  + (wm * 64) * LDA;
        const __half* b1W = sB1 + s * B1_SLAB + wn * 16;
        const __half* b2W = sB2 + s * B1_SLAB + wn * 16;
        #pragma unroll
        for (int kk = 0; kk < BK / 16; kk++) {
            wmma::fragment<wmma::matrix_a, 16, 16, 16, __half, wmma::row_major> a[4];
            #pragma unroll
            for (int i = 0; i < 4; i++)
                wmma::load_matrix_sync(a[i], aW + i * 16 * LDA + kk * 16, LDA);
            {
                wmma::fragment<wmma::matrix_b, 16, 16, 16, __half, wmma::row_major> b;
                wmma::load_matrix_sync(b, b1W + kk * 16 * LDB1, LDB1);
                #pragma unroll
                for (int i = 0; i < 4; i++)
                    wmma::mma_sync(c1[i], a[i], b, c1[i]);
            }
            {
                wmma::fragment<wmma::matrix_b, 16, 16, 16, __half, wmma::row_major> b;
                wmma::load_matrix_sync(b, b2W + kk * 16 * LDB1, LDB1);
                #pragma unroll
                for (int i = 0; i < 4; i++)
                    wmma::mma_sync(c2[i], a[i], b, c2[i]);
            }
        }

        if (kt < 16) w3d[w3i] = pack4(w3v);
        if (++s == 3) s = 0;
        // no bottom barrier: next iteration's top sync orders stage reuse
    }

    // Epilogue: silu(c1)*c2 -> fp16 y via per-warp 64x16 fp32 smem patch
    __syncthreads();
    float* pw = (float*)smem + warp * (64 * 16);
    #pragma unroll
    for (int i = 0; i < 4; i++) {
        #pragma unroll
        for (int t = 0; t < c1[i].num_elements; t++)
            c1[i].x[t] = silu_mul(c1[i].x[t], c2[i].x[t]);
        wmma::store_matrix_sync(pw + i * 16 * 16, c1[i], 16, wmma::mem_row_major);
    }
    __syncwarp();
    __half* yb = g_hy + (size_t)e * T_ * H_ + (size_t)(m0 + wm * 64) * H_ + n0 + wn * 16;
    #pragma unroll
    for (int i = 0; i < 16; i++) {
        int u = lane + i * 32;
        int row = u >> 3, col2 = u & 7;
        float2 v = *(float2*)(pw + row * 16 + col2 * 2);
        *(__half2*)(yb + (size_t)row * H_ + col2 * 2) = __floats2half2_rn(v.x, v.y);
    }
}

// =====================================================================
// Kernel 2: out = y @ W3   (all fp16 operands)
// 256 threads, 8 warps (2M x 4N). Warp tile 64x32. 2 CTAs/SM.
// Grid: (T/BM, D/BN2, E) = (8, 16, 8) = 1024 CTAs
// =====================================================================
__global__ void __launch_bounds__(256, 2)
ffn_down_h(float* __restrict__ Out)
{
    extern __shared__ __align__(128) __half smem[];
    __half* sA = smem;                 // [STG][A_SLAB]
    __half* sB = sA + STG * A_SLAB;    // [STG][B2_SLAB]

    const int tid  = threadIdx.x;
    const int warp = tid >> 5;
    const int wm   = warp >> 2;   // 0..1
    const int wn   = warp & 3;    // 0..3
    const int e  = blockIdx.z;
    const int m0 = blockIdx.x * BM;
    const int n0 = blockIdx.y * BN2;
    const __half* Ay = g_hy  + (size_t)e * T_ * H_;
    const __half* Bg = g_hw3 + (size_t)e * H_ * D_;

    wmma::fragment<wmma::accumulator, 16, 16, 16, float> c[4][2];
    #pragma unroll
    for (int i = 0; i < 4; i++)
        #pragma unroll
        for (int j = 0; j < 2; j++)
            wmma::fill_fragment(c[i][j], 0.0f);

    auto load = [&](int s, int kt) {
        const int k0 = kt * BK;
        #pragma unroll
        for (int i = 0; i < 4; i++) {
            int u = tid + i * 256;
            int row = u >> 3, ch = u & 7;
            cp_async16(sA + s * A_SLAB + row * LDA + ch * 8,
                       Ay + (size_t)(m0 + row) * H_ + k0 + ch * 8);
        }
        #pragma unroll
        for (int i = 0; i < 4; i++) {
            int u = tid + i * 256;
            int r = u >> 4, ch = u & 15;
            cp_async16(sB + s * B2_SLAB + r * LDB2 + ch * 8,
                       Bg + (size_t)(k0 + r) * D_ + n0 + ch * 8);
        }
        cp_commit();
    };

    load(0, 0);
    load(1, 1);

    int s = 0, sl = 2;          // manual stage rotation
    for (int kt = 0; kt < NK2; kt++) {
        if (kt + 1 < NK2) cp_wait<1>(); else cp_wait<0>();
        __syncthreads();
        if (kt + 2 < NK2) {
            load(sl, kt + 2);
            if (++sl == 3) sl = 0;
        }

        const __half* aW = sA + s * A_SLAB  + (wm * 64) * LDA;
        const __half* bW = sB + s * B2_SLAB + wn * 32;
        #pragma unroll
        for (int kk = 0; kk < BK / 16; kk++) {
            wmma::fragment<wmma::matrix_a, 16, 16, 16, __half, wmma::row_major> a[4];
            #pragma unroll
            for (int i = 0; i < 4; i++)
                wmma::load_matrix_sync(a[i], aW + i * 16 * LDA + kk * 16, LDA);
            wmma::fragment<wmma::matrix_b, 16, 16, 16, __half, wmma::row_major> b[2];
            #pragma unroll
            for (int j = 0; j < 2; j++)
                wmma::load_matrix_sync(b[j], bW + kk * 16 * LDB2 + j * 16, LDB2);
            #pragma unroll
            for (int i = 0; i < 4; i++)
                #pragma unroll
                for (int j = 0; j < 2; j++)
                    wmma::mma_sync(c[i][j], a[i], b[j], c[i][j]);
        }
        if (++s == 3) s = 0;
        // no bottom barrier
    }

    #pragma unroll
    for (int i = 0; i < 4; i++)
        #pragma unroll
        for (int j = 0; j < 2; j++)
            wmma::store_matrix_sync(
                Out + (size_t)e * T_ * D_
                    + (size_t)(m0 + wm * 64 + i * 16) * D_ + (n0 + wn * 32 + j * 16),
                c[i][j], D_, wmma::mem_row_major);
}

// =====================================================================
extern "C" void kernel_launch(void* const* d_in, const int* in_sizes, int n_in,
                              void* d_out, int out_size)
{
    const float* x  = (const float*)d_in[0];
    const float* w1 = (const float*)d_in[1];
    const float* w2 = (const float*)d_in[2];
    const float* w3 = (const float*)d_in[3];
    float* out = (float*)d_out;
    (void)in_sizes; (void)n_in; (void)out_size;

    cudaFuncSetAttribute(ffn_gate_h, cudaFuncAttributeMaxDynamicSharedMemorySize, (int)SMEM1);
    cudaFuncSetAttribute(ffn_down_h, cudaFuncAttributeMaxDynamicSharedMemorySize, (int)SMEM2);

    constexpr size_t HALF = TOT3P / 2;
    cvt3_kernel<<<(int)((HALF + 255) / 256), 256>>>(x, w1, w2);

    dim3 g1(T_ / BM, H_ / BN1, E_);        // (8, 88, 8)
    ffn_gate_h<<<g1, 256, SMEM1>>>(w3);

    dim3 g2(T_ / BM, D_ / BN2, E_);        // (8, 16, 8)
    ffn_down_h<<<g2, 256, SMEM2>>>(out);
}